// round 4
// baseline (speedup 1.0000x reference)
#include <cuda_runtime.h>
#include <math.h>

#define Ssz 256
#define Bsz 256
#define Isz 256
#define Hsz 512
#define BH  (Bsz * Hsz)          // 131072
#define G4  2048
#define NCTA 128
#define NTHR 256

// ---------------------------------------------------------------------------
// Device-global scratch (static; no runtime allocations anywhere)
// ---------------------------------------------------------------------------
__device__ float d_h[2][BH];              // masked carried h per layer
__device__ float d_h0un[BH];              // layer0 unmasked h (input to layer1)
__device__ float d_c[2][BH];              // masked carried c per layer
__device__ float d_gpA[4][Bsz * G4];      // K-slot partials, layer0
__device__ float d_gpB[4][Bsz * G4];      // K-slot partials, layer1
__device__ float d_bias[2][G4];           // b_ih + b_hh per layer
__device__ unsigned d_bar_arrive = 0;
__device__ unsigned d_bar_gen = 0;

// ---------------------------------------------------------------------------
// Grid-wide barrier (all 128 CTAs co-resident: 1 CTA/SM on a 148-SM chip)
// ---------------------------------------------------------------------------
__device__ __forceinline__ void gridbar() {
    __threadfence();               // every thread: publish my stores gpu-wide
    __syncthreads();
    if (threadIdx.x == 0) {
        unsigned g = *(volatile unsigned*)&d_bar_gen;
        if (atomicAdd(&d_bar_arrive, 1u) == NCTA - 1) {
            d_bar_arrive = 0;      // safe: everyone has arrived
            __threadfence();
            atomicExch(&d_bar_gen, g + 1);
        } else {
            while (*(volatile unsigned*)&d_bar_gen == g) __nanosleep(64);
        }
    }
    __syncthreads();
}

// ---------------------------------------------------------------------------
// Packed fp32x2 helpers
// ---------------------------------------------------------------------------
__device__ __forceinline__ void ffma2(unsigned long long& d,
                                      unsigned long long a,
                                      unsigned long long b) {
    asm("fma.rn.f32x2 %0, %1, %2, %3;" : "=l"(d) : "l"(a), "l"(b), "l"(d));
}
__device__ __forceinline__ unsigned long long dup_f32(float v) {
    unsigned long long r;
    unsigned int u = __float_as_uint(v);
    asm("mov.b64 %0, {%1, %1};" : "=l"(r) : "r"(u));
    return r;
}

__device__ __forceinline__ float sigf(float x) {
    return 1.0f / (1.0f + __expf(-x));
}
__device__ __forceinline__ float tanhfast(float x) {
    // tanh(x) = 1 - 2/(e^{2x}+1); saturates correctly at +/-inf
    return 1.0f - 2.0f / (__expf(2.0f * x) + 1.0f);
}

// ---------------------------------------------------------------------------
// One 128x128 output tile of gates += Acat * Wcat^T over this CTA's K-slot.
// Acat = [A1 (K1 cols) | A2], Wcat likewise. Slot boundaries are 16-aligned
// w.r.t. K1, so each 16-k chunk has a single source. A is read via .cg
// (cross-CTA produced), W via __ldg (read-only inputs).
// ---------------------------------------------------------------------------
__device__ void gemm_tile(float (*As)[132], float (*Ws)[132],
    const float* __restrict__ A1, int a1s, int K1,
    const float* __restrict__ A2, int a2s,
    const float* __restrict__ W1, int w1s,
    const float* __restrict__ W2, int w2s,
    int kn, float* __restrict__ gbase)
{
    const int tid = threadIdx.x;
    const int bid = blockIdx.x;
    const int ks  = bid >> 5;                   // 0..3
    const int k0  = ks * kn;
    const int mbase = ((bid >> 4) & 1) * 128;   // batch tile
    const int nbase = (bid & 15) * 128;         // gate-col tile
    const int tx = tid & 15;
    const int ty = tid >> 4;
    const int r0 = tid >> 2;                    // 0..63
    const int c0q = (tid & 3) * 4;
    const int r1 = r0 + 64;

    unsigned long long acc[4][8];
#pragma unroll
    for (int i = 0; i < 4; i++)
#pragma unroll
        for (int j = 0; j < 8; j++) acc[i][j] = 0ull;

    const int nch = kn >> 4;

    // chunk source select + first prefetch
    const float *Ab, *Wb; int Ast, Wst;
    {
        int gk = k0;
        if (gk < K1) { Ab = A1 + gk; Ast = a1s; Wb = W1 + gk; Wst = w1s; }
        else { Ab = A2 + (gk - K1); Ast = a2s; Wb = W2 + (gk - K1); Wst = w2s; }
    }
    float4 pa0 = __ldcg((const float4*)(Ab + (size_t)(mbase + r0) * Ast + c0q));
    float4 pa1 = __ldcg((const float4*)(Ab + (size_t)(mbase + r1) * Ast + c0q));
    float4 pw0 = __ldg((const float4*)(Wb + (size_t)(nbase + r0) * Wst + c0q));
    float4 pw1 = __ldg((const float4*)(Wb + (size_t)(nbase + r1) * Wst + c0q));

    for (int ch = 0; ch < nch; ch++) {
        __syncthreads();
        As[c0q + 0][r0] = pa0.x; As[c0q + 1][r0] = pa0.y;
        As[c0q + 2][r0] = pa0.z; As[c0q + 3][r0] = pa0.w;
        As[c0q + 0][r1] = pa1.x; As[c0q + 1][r1] = pa1.y;
        As[c0q + 2][r1] = pa1.z; As[c0q + 3][r1] = pa1.w;
        Ws[c0q + 0][r0] = pw0.x; Ws[c0q + 1][r0] = pw0.y;
        Ws[c0q + 2][r0] = pw0.z; Ws[c0q + 3][r0] = pw0.w;
        Ws[c0q + 0][r1] = pw1.x; Ws[c0q + 1][r1] = pw1.y;
        Ws[c0q + 2][r1] = pw1.z; Ws[c0q + 3][r1] = pw1.w;
        __syncthreads();

        if (ch + 1 < nch) {
            int gk = k0 + (ch + 1) * 16;
            const float *Ab2, *Wb2; int Ast2, Wst2;
            if (gk < K1) { Ab2 = A1 + gk; Ast2 = a1s; Wb2 = W1 + gk; Wst2 = w1s; }
            else { Ab2 = A2 + (gk - K1); Ast2 = a2s; Wb2 = W2 + (gk - K1); Wst2 = w2s; }
            pa0 = __ldcg((const float4*)(Ab2 + (size_t)(mbase + r0) * Ast2 + c0q));
            pa1 = __ldcg((const float4*)(Ab2 + (size_t)(mbase + r1) * Ast2 + c0q));
            pw0 = __ldg((const float4*)(Wb2 + (size_t)(nbase + r0) * Wst2 + c0q));
            pw1 = __ldg((const float4*)(Wb2 + (size_t)(nbase + r1) * Wst2 + c0q));
        }

#pragma unroll
        for (int kk = 0; kk < 16; kk++) {
            const unsigned long long* ap =
                (const unsigned long long*)&As[kk][ty * 8];
            unsigned long long a2_0 = ap[0];
            unsigned long long a2_1 = ap[1];
            unsigned long long a2_2 = ap[2];
            unsigned long long a2_3 = ap[3];

            const float* wp = &Ws[kk][tx * 8];
            float4 wv0 = *(const float4*)wp;
            float4 wv1 = *(const float4*)(wp + 4);
            unsigned long long wd[8];
            wd[0] = dup_f32(wv0.x); wd[1] = dup_f32(wv0.y);
            wd[2] = dup_f32(wv0.z); wd[3] = dup_f32(wv0.w);
            wd[4] = dup_f32(wv1.x); wd[5] = dup_f32(wv1.y);
            wd[6] = dup_f32(wv1.z); wd[7] = dup_f32(wv1.w);

#pragma unroll
            for (int j = 0; j < 8; j++) {
                ffma2(acc[0][j], a2_0, wd[j]);
                ffma2(acc[1][j], a2_1, wd[j]);
                ffma2(acc[2][j], a2_2, wd[j]);
                ffma2(acc[3][j], a2_3, wd[j]);
            }
        }
    }

    float* out = gbase + (size_t)ks * (Bsz * G4);
#pragma unroll
    for (int i2 = 0; i2 < 4; i2++) {
        const int m = mbase + ty * 8 + 2 * i2;
#pragma unroll
        for (int j = 0; j < 8; j++) {
            float2 v = *(float2*)&acc[i2][j];
            const int n = nbase + tx * 8 + j;
            out[(size_t)m * G4 + n]       = v.x;
            out[(size_t)(m + 1) * G4 + n] = v.y;
        }
    }
}

// ---------------------------------------------------------------------------
// Cell: reduce 4 K-slot partials + bias, apply LSTM gates + done-mask.
// Thread tg handles 4 consecutive (b, j) elements (same mapping every step).
// ---------------------------------------------------------------------------
__device__ void cell_phase(const float (*gp)[Bsz * G4],
                           const float* __restrict__ bias,
                           const float* __restrict__ done_t,
                           float* __restrict__ out_un, int layer)
{
    const int tg = blockIdx.x * NTHR + threadIdx.x;  // 0..32767
    const int idx = tg * 4;
    const int b = idx >> 9;
    const int j = idx & 511;
    const float m = 1.0f - __ldg(done_t + b);

    float4 G[4];
#pragma unroll
    for (int g = 0; g < 4; g++) {
        const size_t o = (size_t)b * G4 + g * 512 + j;
        float4 s0 = __ldcg((const float4*)&gp[0][o]);
        float4 s1 = __ldcg((const float4*)&gp[1][o]);
        float4 s2 = __ldcg((const float4*)&gp[2][o]);
        float4 s3 = __ldcg((const float4*)&gp[3][o]);
        float4 bb = __ldg((const float4*)&bias[g * 512 + j]);
        G[g].x = s0.x + s1.x + s2.x + s3.x + bb.x;
        G[g].y = s0.y + s1.y + s2.y + s3.y + bb.y;
        G[g].z = s0.z + s1.z + s2.z + s3.z + bb.z;
        G[g].w = s0.w + s1.w + s2.w + s3.w + bb.w;
    }

    float4 cp = __ldcg((const float4*)&d_c[layer][idx]);
    float4 hn, hm, cm;
    {
        float cn;
        cn   = sigf(G[1].x) * cp.x + sigf(G[0].x) * tanhfast(G[2].x);
        hn.x = sigf(G[3].x) * tanhfast(cn);  cm.x = cn * m;
        cn   = sigf(G[1].y) * cp.y + sigf(G[0].y) * tanhfast(G[2].y);
        hn.y = sigf(G[3].y) * tanhfast(cn);  cm.y = cn * m;
        cn   = sigf(G[1].z) * cp.z + sigf(G[0].z) * tanhfast(G[2].z);
        hn.z = sigf(G[3].z) * tanhfast(cn);  cm.z = cn * m;
        cn   = sigf(G[1].w) * cp.w + sigf(G[0].w) * tanhfast(G[2].w);
        hn.w = sigf(G[3].w) * tanhfast(cn);  cm.w = cn * m;
    }
    hm.x = hn.x * m; hm.y = hn.y * m; hm.z = hn.z * m; hm.w = hn.w * m;

    __stcg((float4*)(out_un + idx), hn);          // unmasked output
    __stcg((float4*)&d_h[layer][idx], hm);        // masked carry
    __stcg((float4*)&d_c[layer][idx], cm);
}

// ---------------------------------------------------------------------------
__global__ __launch_bounds__(NTHR, 1) void lstm_persistent(
    const float* __restrict__ x,    const float* __restrict__ h0,
    const float* __restrict__ c0,   const float* __restrict__ done,
    const float* __restrict__ Wih0, const float* __restrict__ Whh0,
    const float* __restrict__ bih0, const float* __restrict__ bhh0,
    const float* __restrict__ Wih1, const float* __restrict__ Whh1,
    const float* __restrict__ bih1, const float* __restrict__ bhh1,
    float* __restrict__ out)
{
    __shared__ __align__(16) float As[16][132];
    __shared__ __align__(16) float Ws[16][132];

    const int tg = blockIdx.x * NTHR + threadIdx.x;

    // ---- init: state from h0/c0, fused biases
    {
        const int idx = tg * 4;
#pragma unroll
        for (int l = 0; l < 2; l++) {
            float4 hv = __ldg((const float4*)(h0 + (size_t)l * BH + idx));
            float4 cv = __ldg((const float4*)(c0 + (size_t)l * BH + idx));
            __stcg((float4*)&d_h[l][idx], hv);
            __stcg((float4*)&d_c[l][idx], cv);
        }
        if (tg < 1024) {
            const int l = tg >> 9;
            const int c4 = (tg & 511) * 4;
            const float* bi = l ? bih1 : bih0;
            const float* bh = l ? bhh1 : bhh0;
            float4 a = __ldg((const float4*)(bi + c4));
            float4 b = __ldg((const float4*)(bh + c4));
            float4 r;
            r.x = a.x + b.x; r.y = a.y + b.y; r.z = a.z + b.z; r.w = a.w + b.w;
            __stcg((float4*)&d_bias[l][c4], r);
        }
    }
    gridbar();

    for (int t = 0; t < Ssz; t++) {
        // L0: gates = [x_t | h0] * [Wih0 | Whh0]^T, K=768 in 4 slots of 192
        gemm_tile(As, Ws,
                  x + (size_t)t * Bsz * Isz, Isz, Isz,
                  d_h[0], Hsz,
                  Wih0, Isz, Whh0, Hsz,
                  192, &d_gpA[0][0]);
        gridbar();   // A
        cell_phase(d_gpA, d_bias[0], done + (size_t)t * Bsz, d_h0un, 0);
        gridbar();   // B
        // L1: gates = [h0un | h1] * [Wih1 | Whh1]^T, K=1024 in 4 slots of 256
        gemm_tile(As, Ws,
                  d_h0un, Hsz, Hsz,
                  d_h[1], Hsz,
                  Wih1, Hsz, Whh1, Hsz,
                  256, &d_gpB[0][0]);
        gridbar();   // C
        cell_phase(d_gpB, d_bias[1], done + (size_t)t * Bsz,
                   out + (size_t)t * BH, 1);
        // no barrier: next iteration's gemm0 (writes gpA, reads d_h[0]/x)
        // cannot conflict with concurrent cell1 (reads gpB, writes d_h[1]/out)
    }

    // ---- final h, c sections (same thread wrote these addresses)
    {
        const int idx = tg * 4;
#pragma unroll
        for (int l = 0; l < 2; l++) {
            float4 hv = __ldcg((const float4*)&d_h[l][idx]);
            float4 cv = __ldcg((const float4*)&d_c[l][idx]);
            *(float4*)(out + (size_t)Ssz * BH + (size_t)l * BH + idx) = hv;
            *(float4*)(out + (size_t)Ssz * BH + (size_t)2 * BH
                           + (size_t)l * BH + idx) = cv;
        }
    }
}

// ---------------------------------------------------------------------------
extern "C" void kernel_launch(void* const* d_in, const int* in_sizes, int n_in,
                              void* d_out, int out_size)
{
    const float* x    = (const float*)d_in[0];
    const float* h0   = (const float*)d_in[1];
    const float* c0   = (const float*)d_in[2];
    const float* done = (const float*)d_in[3];
    const float* Wih0 = (const float*)d_in[4];
    const float* Whh0 = (const float*)d_in[5];
    const float* bih0 = (const float*)d_in[6];
    const float* bhh0 = (const float*)d_in[7];
    const float* Wih1 = (const float*)d_in[8];
    const float* Whh1 = (const float*)d_in[9];
    const float* bih1 = (const float*)d_in[10];
    const float* bhh1 = (const float*)d_in[11];
    float* out = (float*)d_out;

    lstm_persistent<<<NCTA, NTHR>>>(x, h0, c0, done,
                                    Wih0, Whh0, bih0, bhh0,
                                    Wih1, Whh1, bih1, bhh1, out);
}

// round 6
// speedup vs baseline: 2.0986x; 2.0986x over previous
#include <cuda_runtime.h>
#include <cuda_bf16.h>
#include <stdint.h>
#include <math.h>

#define Ssz 256
#define Bsz 256
#define Isz 256
#define Hsz 512
#define BH  (Bsz * Hsz)          // 131072
#define G4  2048
#define SBI (Ssz * Bsz * Isz)    // 16777216
#define NCTA 128
#define NTHR 256
#define GPSTRIDE (Bsz * G4)      // 524288

// SMEM layout (dynamic, 1024-aligned base): 4 x 16KB chunk buffers
#define OFF_AH   0
#define OFF_AL   16384
#define OFF_WH   32768
#define OFF_WL   49152
#define SMEM_DYN (1024 + 65536)

// ---------------------------------------------------------------------------
// Device-global scratch (static; no runtime allocations)
// ---------------------------------------------------------------------------
__device__ float           d_h[2][BH];        // masked h, fp32 (final output)
__device__ float           d_c[2][BH];        // masked c, fp32
__device__ __nv_bfloat16   d_hh[2][BH], d_hl[2][BH];   // masked h bf16 hi/lo
__device__ __nv_bfloat16   d_unh[BH], d_unl[BH];       // layer0 unmasked h hi/lo
__device__ __nv_bfloat16   d_xh[SBI], d_xl[SBI];       // x split
__device__ __nv_bfloat16   d_W0h[G4 * 768],  d_W0l[G4 * 768];   // [Wih0|Whh0]
__device__ __nv_bfloat16   d_W1h[G4 * 1024], d_W1l[G4 * 1024];  // [Wih1|Whh1]
__device__ float           d_gpA[4][GPSTRIDE];  // K-slot partials, layer0
__device__ float           d_gpB[4][GPSTRIDE];  // K-slot partials, layer1
__device__ float           d_bias[2][G4];
__device__ unsigned        d_bar_arrive = 0;
__device__ unsigned        d_bar_gen = 0;

// ---------------------------------------------------------------------------
// Grid-wide barrier (128 CTAs, 1/SM on 148-SM chip -> co-resident)
// ---------------------------------------------------------------------------
__device__ __forceinline__ void gridbar() {
    __threadfence();
    __syncthreads();
    if (threadIdx.x == 0) {
        unsigned g = *(volatile unsigned*)&d_bar_gen;
        if (atomicAdd(&d_bar_arrive, 1u) == NCTA - 1) {
            d_bar_arrive = 0;
            __threadfence();
            atomicExch(&d_bar_gen, g + 1);
        } else {
            while (*(volatile unsigned*)&d_bar_gen == g) __nanosleep(64);
        }
    }
    __syncthreads();
}

// ---------------------------------------------------------------------------
// Warp MMA primitives (sm_80+ PTX; no arch-suffix features)
// ---------------------------------------------------------------------------
#define LDSM_X4(r0, r1, r2, r3, addr)                                         \
    asm volatile("ldmatrix.sync.aligned.m8n8.x4.shared.b16 "                  \
                 "{%0, %1, %2, %3}, [%4];"                                    \
                 : "=r"(r0), "=r"(r1), "=r"(r2), "=r"(r3) : "r"(addr))

#define LDSM_X2(r0, r1, addr)                                                 \
    asm volatile("ldmatrix.sync.aligned.m8n8.x2.shared.b16 "                  \
                 "{%0, %1}, [%2];"                                            \
                 : "=r"(r0), "=r"(r1) : "r"(addr))

#define MMA_BF16(c, a, b)                                                     \
    asm volatile("mma.sync.aligned.m16n8k16.row.col.f32.bf16.bf16.f32 "       \
                 "{%0, %1, %2, %3}, {%4, %5, %6, %7}, {%8, %9}, "             \
                 "{%0, %1, %2, %3};"                                          \
                 : "+f"((c)[0]), "+f"((c)[1]), "+f"((c)[2]), "+f"((c)[3])     \
                 : "r"((a)[0]), "r"((a)[1]), "r"((a)[2]), "r"((a)[3]),        \
                   "r"((b)[0]), "r"((b)[1]))

__device__ __forceinline__ uint32_t swz(uint32_t bo) {
    return bo ^ ((bo >> 3) & 0x70);
}

// ---------------------------------------------------------------------------
// bf16 split helpers
// ---------------------------------------------------------------------------
__device__ __forceinline__ void split1(float v, __nv_bfloat16& h, __nv_bfloat16& l) {
    h = __float2bfloat16_rn(v);
    l = __float2bfloat16_rn(v - __bfloat162float(h));
}
__device__ __forceinline__ void split4(float4 v, uint2& hi, uint2& lo) {
    __nv_bfloat16 h0, h1, h2, h3, l0, l1, l2, l3;
    split1(v.x, h0, l0); split1(v.y, h1, l1);
    split1(v.z, h2, l2); split1(v.w, h3, l3);
    __nv_bfloat162 ph0(h0, h1), ph1(h2, h3), pl0(l0, l1), pl1(l2, l3);
    hi.x = *(uint32_t*)&ph0; hi.y = *(uint32_t*)&ph1;
    lo.x = *(uint32_t*)&pl0; lo.y = *(uint32_t*)&pl1;
}

__device__ __forceinline__ float sigf(float x) { return 1.0f / (1.0f + __expf(-x)); }
__device__ __forceinline__ float tanhfast(float x) {
    return 1.0f - 2.0f / (__expf(2.0f * x) + 1.0f);
}

// ---------------------------------------------------------------------------
// Load one 64-k chunk: A (hi,lo) 128 rows + W (hi,lo) 128 rows into SW128
// swizzled 128B-row smem buffers. 16B units; each thread 4 units per buffer.
// ---------------------------------------------------------------------------
__device__ __forceinline__ void load_chunk(char* sm,
    const __nv_bfloat16* __restrict__ Ah, const __nv_bfloat16* __restrict__ Al,
    int sA,
    const __nv_bfloat16* __restrict__ Wh, const __nv_bfloat16* __restrict__ Wl,
    int sW, int mbase, int nbase)
{
    const int tid = threadIdx.x;
#pragma unroll
    for (int q = 0; q < 4; q++) {
        const int u = tid * 4 + q;
        const int row = u >> 3;
        const int c16 = u & 7;
        const uint32_t sw = swz(row * 128 + c16 * 16);
        const size_t aoff = (size_t)(mbase + row) * sA + c16 * 8;
        const size_t woff = (size_t)(nbase + row) * sW + c16 * 8;
        uint4 vah = __ldcg((const uint4*)(Ah + aoff));
        uint4 val = __ldcg((const uint4*)(Al + aoff));
        uint4 vwh = __ldg((const uint4*)(Wh + woff));
        uint4 vwl = __ldg((const uint4*)(Wl + woff));
        *(uint4*)(sm + OFF_AH + sw) = vah;
        *(uint4*)(sm + OFF_AL + sw) = val;
        *(uint4*)(sm + OFF_WH + sw) = vwh;
        *(uint4*)(sm + OFF_WL + sw) = vwl;
    }
}

// ---------------------------------------------------------------------------
// One gate GEMM for this CTA's (m-tile, n-tile, K-slot) via bf16 split
// warp MMAs. acc layout: [mf][nf][4], warp tile 64x32.
// ---------------------------------------------------------------------------
__device__ void gemm_mma(char* sm, uint32_t sb, int nch, int layer, int t,
                         float* __restrict__ gp)
{
    const int bid = blockIdx.x;
    const int ks = bid >> 5;
    const int mbase = ((bid >> 4) & 1) * 128;
    const int nbase = (bid & 15) * 128;
    const int tid = threadIdx.x;
    const int wid = tid >> 5;
    const int lane = tid & 31;
    const int wm = (wid >> 2) * 64;      // 0 | 64
    const int wn = (wid & 3) * 32;       // 0,32,64,96
    const int K = layer ? 1024 : 768;
    const __nv_bfloat16* Whg = layer ? d_W1h : d_W0h;
    const __nv_bfloat16* Wlg = layer ? d_W1l : d_W0l;

    float acc[4][4][4];
#pragma unroll
    for (int mf = 0; mf < 4; mf++)
#pragma unroll
        for (int nf = 0; nf < 4; nf++)
#pragma unroll
            for (int e = 0; e < 4; e++) acc[mf][nf][e] = 0.0f;

    // per-lane ldmatrix base offsets (row-adds of 16/8 rows are swizzle-
    // invariant: they only touch bits >= 10 of the byte offset)
    // A: lanes 0-15 -> rows 0-15 @k-lo16B, lanes 16-31 -> rows 0-15 @k-hi16B
    const uint32_t a_bo0 = (uint32_t)(wm + (lane & 15)) * 128 + ((lane >> 4) << 4);
    // B: lanes 0-7 -> rows @k-lo, lanes 8-15 -> rows @k-hi
    const uint32_t b_bo0 = (uint32_t)(wn + (lane & 7)) * 128 + (((lane >> 3) & 1) << 4);

    for (int ci = 0; ci < nch; ci++) {
        const int gck = ks * nch + ci;
        const __nv_bfloat16 *Ah, *Al; int sA;
        if (layer == 0) {
            if (gck < 4) {
                Ah = d_xh + (size_t)t * (Bsz * Isz) + 64 * gck;
                Al = d_xl + (size_t)t * (Bsz * Isz) + 64 * gck; sA = Isz;
            } else {
                Ah = d_hh[0] + 64 * (gck - 4);
                Al = d_hl[0] + 64 * (gck - 4); sA = Hsz;
            }
        } else {
            if (gck < 8) {
                Ah = d_unh + 64 * gck; Al = d_unl + 64 * gck; sA = Hsz;
            } else {
                Ah = d_hh[1] + 64 * (gck - 8);
                Al = d_hl[1] + 64 * (gck - 8); sA = Hsz;
            }
        }
        load_chunk(sm, Ah, Al, sA, Whg + 64 * gck, Wlg + 64 * gck, K,
                   mbase, nbase);
        __syncthreads();

#pragma unroll
        for (int k16 = 0; k16 < 4; k16++) {
            const uint32_t asw = sb + swz(a_bo0 + k16 * 32);
            const uint32_t bsw = sb + swz(b_bo0 + k16 * 32);

            uint32_t fAh[4][4], fAl[4][4], fBh[4][2], fBl[4][2];
#pragma unroll
            for (int mf = 0; mf < 4; mf++) {
                const uint32_t ao = asw + mf * 2048;   // +16 rows per mf
                LDSM_X4(fAh[mf][0], fAh[mf][1], fAh[mf][2], fAh[mf][3],
                        ao + OFF_AH);
                LDSM_X4(fAl[mf][0], fAl[mf][1], fAl[mf][2], fAl[mf][3],
                        ao + OFF_AL);
            }
#pragma unroll
            for (int nf = 0; nf < 4; nf++) {
                const uint32_t bo = bsw + nf * 1024;   // +8 rows per nf
                LDSM_X2(fBh[nf][0], fBh[nf][1], bo + OFF_WH);
                LDSM_X2(fBl[nf][0], fBl[nf][1], bo + OFF_WL);
            }
#pragma unroll
            for (int mf = 0; mf < 4; mf++)
#pragma unroll
                for (int nf = 0; nf < 4; nf++) {
                    MMA_BF16(acc[mf][nf], fAh[mf], fBh[nf]);
                    MMA_BF16(acc[mf][nf], fAl[mf], fBh[nf]);
                    MMA_BF16(acc[mf][nf], fAh[mf], fBl[nf]);
                }
        }
        __syncthreads();   // all warps done with smem before next chunk load
    }

    // epilogue: acc -> fp32 partial buffer
    float* dst = gp + (size_t)ks * GPSTRIDE;
#pragma unroll
    for (int mf = 0; mf < 4; mf++) {
#pragma unroll
        for (int nf = 0; nf < 4; nf++) {
            const int m0 = mbase + wm + mf * 16 + (lane >> 2);
            const int n0 = nbase + wn + nf * 8 + (lane & 3) * 2;
            float2 v0 = make_float2(acc[mf][nf][0], acc[mf][nf][1]);
            float2 v1 = make_float2(acc[mf][nf][2], acc[mf][nf][3]);
            __stcg((float2*)(dst + (size_t)m0 * G4 + n0), v0);
            __stcg((float2*)(dst + (size_t)(m0 + 8) * G4 + n0), v1);
        }
    }
}

// ---------------------------------------------------------------------------
// Cell: reduce 4 K-slot partials + bias, LSTM gates + done-mask; emit bf16
// splits of unmasked (layer0) and masked h for next-step GEMMs.
// ---------------------------------------------------------------------------
__device__ void cell_phase(const float* __restrict__ gp,
                           const float* __restrict__ bias,
                           const float* __restrict__ done_t,
                           int layer, float* __restrict__ out_un)
{
    const int tg = blockIdx.x * NTHR + threadIdx.x;   // 0..32767
    const int idx = tg * 4;
    const int b = idx >> 9;
    const int j = idx & 511;
    const float m = 1.0f - __ldg(done_t + b);

    float4 G[4];
#pragma unroll
    for (int g = 0; g < 4; g++) {
        const size_t o = (size_t)b * G4 + g * 512 + j;
        float4 s0 = __ldcg((const float4*)(gp + 0 * (size_t)GPSTRIDE + o));
        float4 s1 = __ldcg((const float4*)(gp + 1 * (size_t)GPSTRIDE + o));
        float4 s2 = __ldcg((const float4*)(gp + 2 * (size_t)GPSTRIDE + o));
        float4 s3 = __ldcg((const float4*)(gp + 3 * (size_t)GPSTRIDE + o));
        float4 bb = __ldg((const float4*)&bias[g * 512 + j]);
        G[g].x = s0.x + s1.x + s2.x + s3.x + bb.x;
        G[g].y = s0.y + s1.y + s2.y + s3.y + bb.y;
        G[g].z = s0.z + s1.z + s2.z + s3.z + bb.z;
        G[g].w = s0.w + s1.w + s2.w + s3.w + bb.w;
    }

    float4 cp = __ldcg((const float4*)&d_c[layer][idx]);
    float4 hn, hm, cm;
    {
        float cn;
        cn   = sigf(G[1].x) * cp.x + sigf(G[0].x) * tanhfast(G[2].x);
        hn.x = sigf(G[3].x) * tanhfast(cn);  cm.x = cn * m;
        cn   = sigf(G[1].y) * cp.y + sigf(G[0].y) * tanhfast(G[2].y);
        hn.y = sigf(G[3].y) * tanhfast(cn);  cm.y = cn * m;
        cn   = sigf(G[1].z) * cp.z + sigf(G[0].z) * tanhfast(G[2].z);
        hn.z = sigf(G[3].z) * tanhfast(cn);  cm.z = cn * m;
        cn   = sigf(G[1].w) * cp.w + sigf(G[0].w) * tanhfast(G[2].w);
        hn.w = sigf(G[3].w) * tanhfast(cn);  cm.w = cn * m;
    }
    hm.x = hn.x * m; hm.y = hn.y * m; hm.z = hn.z * m; hm.w = hn.w * m;

    if (layer == 0) {
        uint2 uh, ul;
        split4(hn, uh, ul);                       // unmasked -> layer1 input
        __stcg((uint2*)&d_unh[idx], uh);
        __stcg((uint2*)&d_unl[idx], ul);
    } else {
        __stcg((float4*)(out_un + idx), hn);      // unmasked -> output slab
    }
    uint2 mh, ml;
    split4(hm, mh, ml);                           // masked carry splits
    __stcg((uint2*)&d_hh[layer][idx], mh);
    __stcg((uint2*)&d_hl[layer][idx], ml);
    __stcg((float4*)&d_h[layer][idx], hm);        // fp32 (final output)
    __stcg((float4*)&d_c[layer][idx], cm);
}

// ---------------------------------------------------------------------------
__global__ __launch_bounds__(NTHR, 1) void lstm_mma(
    const float* __restrict__ x,    const float* __restrict__ h0,
    const float* __restrict__ c0,   const float* __restrict__ done,
    const float* __restrict__ Wih0, const float* __restrict__ Whh0,
    const float* __restrict__ bih0, const float* __restrict__ bhh0,
    const float* __restrict__ Wih1, const float* __restrict__ Whh1,
    const float* __restrict__ bih1, const float* __restrict__ bhh1,
    float* __restrict__ out)
{
    extern __shared__ char smraw[];
    char* sm = (char*)(((uintptr_t)smraw + 1023) & ~(uintptr_t)1023);
    uint32_t sb;
    asm("{ .reg .u64 t; cvta.to.shared.u64 t, %1; cvt.u32.u64 %0, t; }"
        : "=r"(sb) : "l"(sm));

    const int tid = threadIdx.x;
    const int tg = blockIdx.x * NTHR + tid;

    // ================= prologue: conversions (once per launch) =============
    for (int i4 = tg; i4 < SBI / 4; i4 += NCTA * NTHR) {
        float4 v = __ldg((const float4*)(x + (size_t)i4 * 4));
        uint2 hi, lo;
        split4(v, hi, lo);
        __stcg((uint2*)&d_xh[(size_t)i4 * 4], hi);
        __stcg((uint2*)&d_xl[(size_t)i4 * 4], lo);
    }
    for (int i = tg; i < G4 * 768; i += NCTA * NTHR) {
        const int n = i / 768, k = i - n * 768;
        const float v = (k < 256) ? __ldg(Wih0 + n * 256 + k)
                                  : __ldg(Whh0 + n * 512 + (k - 256));
        __nv_bfloat16 h, l;
        split1(v, h, l);
        d_W0h[i] = h; d_W0l[i] = l;
    }
    for (int i = tg; i < G4 * 1024; i += NCTA * NTHR) {
        const int n = i >> 10, k = i & 1023;
        const float v = (k < 512) ? __ldg(Wih1 + n * 512 + k)
                                  : __ldg(Whh1 + n * 512 + (k - 512));
        __nv_bfloat16 h, l;
        split1(v, h, l);
        d_W1h[i] = h; d_W1l[i] = l;
    }
    {
        const int idx = tg * 4;
#pragma unroll
        for (int l = 0; l < 2; l++) {
            float4 hv = __ldg((const float4*)(h0 + (size_t)l * BH + idx));
            float4 cv = __ldg((const float4*)(c0 + (size_t)l * BH + idx));
            __stcg((float4*)&d_h[l][idx], hv);
            __stcg((float4*)&d_c[l][idx], cv);
            uint2 hi, lo;
            split4(hv, hi, lo);
            __stcg((uint2*)&d_hh[l][idx], hi);
            __stcg((uint2*)&d_hl[l][idx], lo);
        }
        if (tg < 1024) {
            const int l = tg >> 9;
            const int c4 = (tg & 511) * 4;
            const float* bi = l ? bih1 : bih0;
            const float* bh = l ? bhh1 : bhh0;
            float4 a = __ldg((const float4*)(bi + c4));
            float4 b = __ldg((const float4*)(bh + c4));
            float4 r;
            r.x = a.x + b.x; r.y = a.y + b.y; r.z = a.z + b.z; r.w = a.w + b.w;
            __stcg((float4*)&d_bias[l][c4], r);
        }
    }

    gridbar();

    // ================= main recurrence =====================================
    for (int t = 0; t < Ssz; t++) {
        gemm_mma(sm, sb, 3, 0, t, &d_gpA[0][0]);
        gridbar();   // A: gate partials L0 complete
        cell_phase(&d_gpA[0][0], d_bias[0], done + (size_t)t * Bsz, 0, nullptr);
        gridbar();   // B: h0un / h0 splits complete
        gemm_mma(sm, sb, 4, 1, t, &d_gpB[0][0]);
        gridbar();   // C: gate partials L1 complete
        cell_phase(&d_gpB[0][0], d_bias[1], done + (size_t)t * Bsz, 1,
                   out + (size_t)t * BH);
        // no barrier: next gemm0 (writes gpA, reads h[0]/x) is disjoint from
        // concurrent cell1 (reads gpB, writes h[1]/c[1]/out)
    }

    // ================= tail: final h, c ====================================
    {
        const int idx = tg * 4;
#pragma unroll
        for (int l = 0; l < 2; l++) {
            float4 hv = __ldcg((const float4*)&d_h[l][idx]);
            float4 cv = __ldcg((const float4*)&d_c[l][idx]);
            *(float4*)(out + (size_t)Ssz * BH + (size_t)l * BH + idx) = hv;
            *(float4*)(out + (size_t)Ssz * BH + (size_t)2 * BH
                           + (size_t)l * BH + idx) = cv;
        }
    }
}

// ---------------------------------------------------------------------------
extern "C" void kernel_launch(void* const* d_in, const int* in_sizes, int n_in,
                              void* d_out, int out_size)
{
    const float* x    = (const float*)d_in[0];
    const float* h0   = (const float*)d_in[1];
    const float* c0   = (const float*)d_in[2];
    const float* done = (const float*)d_in[3];
    const float* Wih0 = (const float*)d_in[4];
    const float* Whh0 = (const float*)d_in[5];
    const float* bih0 = (const float*)d_in[6];
    const float* bhh0 = (const float*)d_in[7];
    const float* Wih1 = (const float*)d_in[8];
    const float* Whh1 = (const float*)d_in[9];
    const float* bih1 = (const float*)d_in[10];
    const float* bhh1 = (const float*)d_in[11];
    float* out = (float*)d_out;

    cudaFuncSetAttribute(lstm_mma, cudaFuncAttributeMaxDynamicSharedMemorySize,
                         SMEM_DYN);
    lstm_mma<<<NCTA, NTHR, SMEM_DYN>>>(x, h0, c0, done,
                                       Wih0, Whh0, bih0, bhh0,
                                       Wih1, Whh1, bih1, bhh1, out);
}

// round 7
// speedup vs baseline: 2.3971x; 1.1422x over previous
#include <cuda_runtime.h>
#include <cuda_bf16.h>
#include <stdint.h>
#include <math.h>

#define Ssz 256
#define Bsz 256
#define Isz 256
#define Hsz 512
#define BH  (Bsz * Hsz)          // 131072
#define G4  2048
#define SBI (Ssz * Bsz * Isz)    // 16777216
#define NCTA 128
#define NTHR 256
#define GPSTRIDE (Bsz * G4)      // 524288

// SMEM: two 64KB pipeline stages (each: AH|AL|WH|WL 16KB), 1024-aligned base
#define OFF_AH   0
#define OFF_AL   16384
#define OFF_WH   32768
#define OFF_WL   49152
#define STAGE_SZ 65536
#define SMEM_DYN (1024 + 2 * STAGE_SZ)

// ---------------------------------------------------------------------------
// Device-global scratch (static; no runtime allocations)
// ---------------------------------------------------------------------------
__device__ float           d_h[2][BH];        // masked h, fp32 (final output)
__device__ float           d_c[2][BH];        // masked c, fp32
__device__ __nv_bfloat16   d_hh[2][BH], d_hl[2][BH];   // masked h bf16 hi/lo
__device__ __nv_bfloat16   d_unh[BH], d_unl[BH];       // layer0 unmasked h hi/lo
__device__ __nv_bfloat16   d_xh[SBI], d_xl[SBI];       // x split
__device__ __nv_bfloat16   d_W0h[G4 * 768],  d_W0l[G4 * 768];   // [Wih0|Whh0]
__device__ __nv_bfloat16   d_W1h[G4 * 1024], d_W1l[G4 * 1024];  // [Wih1|Whh1]
__device__ float           d_gpA[4][GPSTRIDE];  // K-slot partials, layer0
__device__ float           d_gpB[4][GPSTRIDE];  // K-slot partials, layer1
__device__ float           d_bias[2][G4];
__device__ unsigned        d_bar_arrive = 0;
__device__ unsigned        d_bar_gen = 0;

// ---------------------------------------------------------------------------
// Grid-wide barrier (128 CTAs, 1/SM on 148-SM chip -> co-resident)
// ---------------------------------------------------------------------------
__device__ __forceinline__ void gridbar() {
    __threadfence();
    __syncthreads();
    if (threadIdx.x == 0) {
        unsigned g = *(volatile unsigned*)&d_bar_gen;
        if (atomicAdd(&d_bar_arrive, 1u) == NCTA - 1) {
            d_bar_arrive = 0;
            __threadfence();
            atomicExch(&d_bar_gen, g + 1);
        } else {
            while (*(volatile unsigned*)&d_bar_gen == g) __nanosleep(64);
        }
    }
    __syncthreads();
}

// ---------------------------------------------------------------------------
// Warp MMA + cp.async primitives (sm_80+ PTX; no arch-suffix features)
// ---------------------------------------------------------------------------
#define LDSM_X4(r0, r1, r2, r3, addr)                                         \
    asm volatile("ldmatrix.sync.aligned.m8n8.x4.shared.b16 "                  \
                 "{%0, %1, %2, %3}, [%4];"                                    \
                 : "=r"(r0), "=r"(r1), "=r"(r2), "=r"(r3) : "r"(addr))

#define LDSM_X2(r0, r1, addr)                                                 \
    asm volatile("ldmatrix.sync.aligned.m8n8.x2.shared.b16 "                  \
                 "{%0, %1}, [%2];"                                            \
                 : "=r"(r0), "=r"(r1) : "r"(addr))

#define MMA_BF16(c, a, b)                                                     \
    asm volatile("mma.sync.aligned.m16n8k16.row.col.f32.bf16.bf16.f32 "       \
                 "{%0, %1, %2, %3}, {%4, %5, %6, %7}, {%8, %9}, "             \
                 "{%0, %1, %2, %3};"                                          \
                 : "+f"((c)[0]), "+f"((c)[1]), "+f"((c)[2]), "+f"((c)[3])     \
                 : "r"((a)[0]), "r"((a)[1]), "r"((a)[2]), "r"((a)[3]),        \
                   "r"((b)[0]), "r"((b)[1]))

#define CP16(saddr, gptr)                                                     \
    asm volatile("cp.async.cg.shared.global [%0], [%1], 16;"                  \
                 :: "r"(saddr), "l"(gptr))
#define CP_COMMIT() asm volatile("cp.async.commit_group;")
#define CP_WAIT1()  asm volatile("cp.async.wait_group 1;")
#define CP_WAIT0()  asm volatile("cp.async.wait_group 0;")

__device__ __forceinline__ uint32_t swz(uint32_t bo) {
    return bo ^ ((bo >> 3) & 0x70);
}

// ---------------------------------------------------------------------------
// bf16 split helpers
// ---------------------------------------------------------------------------
__device__ __forceinline__ void split1(float v, __nv_bfloat16& h, __nv_bfloat16& l) {
    h = __float2bfloat16_rn(v);
    l = __float2bfloat16_rn(v - __bfloat162float(h));
}
__device__ __forceinline__ void split4(float4 v, uint2& hi, uint2& lo) {
    __nv_bfloat16 h0, h1, h2, h3, l0, l1, l2, l3;
    split1(v.x, h0, l0); split1(v.y, h1, l1);
    split1(v.z, h2, l2); split1(v.w, h3, l3);
    __nv_bfloat162 ph0(h0, h1), ph1(h2, h3), pl0(l0, l1), pl1(l2, l3);
    hi.x = *(uint32_t*)&ph0; hi.y = *(uint32_t*)&ph1;
    lo.x = *(uint32_t*)&pl0; lo.y = *(uint32_t*)&pl1;
}

__device__ __forceinline__ float sigf(float x) { return 1.0f / (1.0f + __expf(-x)); }
__device__ __forceinline__ float tanhfast(float x) {
    return 1.0f - 2.0f / (__expf(2.0f * x) + 1.0f);
}

// ---------------------------------------------------------------------------
// Resolve the (hi,lo) activation source for global chunk gck of a layer.
// ---------------------------------------------------------------------------
__device__ __forceinline__ void chunk_src(int layer, int t, int gck,
    const __nv_bfloat16*& Ah, const __nv_bfloat16*& Al, int& sA)
{
    if (layer == 0) {
        if (gck < 4) {
            Ah = d_xh + (size_t)t * (Bsz * Isz) + 64 * gck;
            Al = d_xl + (size_t)t * (Bsz * Isz) + 64 * gck; sA = Isz;
        } else {
            Ah = d_hh[0] + 64 * (gck - 4);
            Al = d_hl[0] + 64 * (gck - 4); sA = Hsz;
        }
    } else {
        if (gck < 8) {
            Ah = d_unh + 64 * gck; Al = d_unl + 64 * gck; sA = Hsz;
        } else {
            Ah = d_hh[1] + 64 * (gck - 8);
            Al = d_hl[1] + 64 * (gck - 8); sA = Hsz;
        }
    }
}

// Issue async copy of one 64-k chunk into the given smem stage (16 x 16B per
// thread). No waiting here; caller commits the group.
__device__ __forceinline__ void cp_chunk(uint32_t stg,
    const __nv_bfloat16* __restrict__ Ah, const __nv_bfloat16* __restrict__ Al,
    int sA,
    const __nv_bfloat16* __restrict__ Wh, const __nv_bfloat16* __restrict__ Wl,
    int sW, int mbase, int nbase)
{
    const int tid = threadIdx.x;
#pragma unroll
    for (int q = 0; q < 4; q++) {
        const int u = tid * 4 + q;
        const int row = u >> 3;
        const int c16 = u & 7;
        const uint32_t sw = swz(row * 128 + c16 * 16);
        const size_t aoff = (size_t)(mbase + row) * sA + c16 * 8;
        const size_t woff = (size_t)(nbase + row) * sW + c16 * 8;
        CP16(stg + OFF_AH + sw, Ah + aoff);
        CP16(stg + OFF_AL + sw, Al + aoff);
        CP16(stg + OFF_WH + sw, Wh + woff);
        CP16(stg + OFF_WL + sw, Wl + woff);
    }
}

// ---------------------------------------------------------------------------
// One gate GEMM for this CTA's (m-tile, n-tile, K-slot) via bf16 split warp
// MMAs with a 2-stage cp.async pipeline. Warp tile 64x32, acc [mf][nf][4].
// ---------------------------------------------------------------------------
__device__ void gemm_mma(uint32_t sb, int nch, int layer, int t,
                         float* __restrict__ gp)
{
    const int bid = blockIdx.x;
    const int ks = bid >> 5;
    const int mbase = ((bid >> 4) & 1) * 128;
    const int nbase = (bid & 15) * 128;
    const int tid = threadIdx.x;
    const int wid = tid >> 5;
    const int lane = tid & 31;
    const int wm = (wid >> 2) * 64;      // 0 | 64
    const int wn = (wid & 3) * 32;       // 0,32,64,96
    const int K = layer ? 1024 : 768;
    const __nv_bfloat16* Whg = layer ? d_W1h : d_W0h;
    const __nv_bfloat16* Wlg = layer ? d_W1l : d_W0l;

    float acc[4][4][4];
#pragma unroll
    for (int mf = 0; mf < 4; mf++)
#pragma unroll
        for (int nf = 0; nf < 4; nf++)
#pragma unroll
            for (int e = 0; e < 4; e++) acc[mf][nf][e] = 0.0f;

    // per-lane ldmatrix base offsets (row-adds of 16/8 rows are swizzle-
    // invariant: they only touch bits >= 10 of the byte offset)
    const uint32_t a_bo0 = (uint32_t)(wm + (lane & 15)) * 128 + ((lane >> 4) << 4);
    const uint32_t b_bo0 = (uint32_t)(wn + (lane & 7)) * 128 + (((lane >> 3) & 1) << 4);

    // prologue: issue chunk 0 into stage 0
    {
        const __nv_bfloat16 *Ah, *Al; int sA;
        const int gck = ks * nch;
        chunk_src(layer, t, gck, Ah, Al, sA);
        cp_chunk(sb, Ah, Al, sA, Whg + 64 * gck, Wlg + 64 * gck, K,
                 mbase, nbase);
        CP_COMMIT();
    }

    for (int ci = 0; ci < nch; ci++) {
        if (ci + 1 < nch) {   // issue next chunk into the other stage
            const __nv_bfloat16 *Ah, *Al; int sA;
            const int gck = ks * nch + ci + 1;
            chunk_src(layer, t, gck, Ah, Al, sA);
            cp_chunk(sb + ((ci + 1) & 1) * STAGE_SZ, Ah, Al, sA,
                     Whg + 64 * gck, Wlg + 64 * gck, K, mbase, nbase);
            CP_COMMIT();
            CP_WAIT1();       // chunk ci's group complete (mine)
        } else {
            CP_WAIT0();
        }
        __syncthreads();       // everyone's chunk ci data visible

        const uint32_t stg = sb + (ci & 1) * STAGE_SZ;
#pragma unroll
        for (int k16 = 0; k16 < 4; k16++) {
            const uint32_t asw = stg + swz(a_bo0 + k16 * 32);
            const uint32_t bsw = stg + swz(b_bo0 + k16 * 32);

            uint32_t fAh[4][4], fAl[4][4], fBh[4][2], fBl[4][2];
#pragma unroll
            for (int mf = 0; mf < 4; mf++) {
                const uint32_t ao = asw + mf * 2048;   // +16 rows per mf
                LDSM_X4(fAh[mf][0], fAh[mf][1], fAh[mf][2], fAh[mf][3],
                        ao + OFF_AH);
                LDSM_X4(fAl[mf][0], fAl[mf][1], fAl[mf][2], fAl[mf][3],
                        ao + OFF_AL);
            }
#pragma unroll
            for (int nf = 0; nf < 4; nf++) {
                const uint32_t bo = bsw + nf * 1024;   // +8 rows per nf
                LDSM_X2(fBh[nf][0], fBh[nf][1], bo + OFF_WH);
                LDSM_X2(fBl[nf][0], fBl[nf][1], bo + OFF_WL);
            }
#pragma unroll
            for (int mf = 0; mf < 4; mf++)
#pragma unroll
                for (int nf = 0; nf < 4; nf++) {
                    MMA_BF16(acc[mf][nf], fAh[mf], fBh[nf]);
                    MMA_BF16(acc[mf][nf], fAl[mf], fBh[nf]);
                    MMA_BF16(acc[mf][nf], fAh[mf], fBl[nf]);
                }
        }
        __syncthreads();   // all warps done reading stage ci before reuse
    }

    // epilogue: acc -> fp32 partial buffer
    float* dst = gp + (size_t)ks * GPSTRIDE;
#pragma unroll
    for (int mf = 0; mf < 4; mf++) {
#pragma unroll
        for (int nf = 0; nf < 4; nf++) {
            const int m0 = mbase + wm + mf * 16 + (lane >> 2);
            const int n0 = nbase + wn + nf * 8 + (lane & 3) * 2;
            float2 v0 = make_float2(acc[mf][nf][0], acc[mf][nf][1]);
            float2 v1 = make_float2(acc[mf][nf][2], acc[mf][nf][3]);
            __stcg((float2*)(dst + (size_t)m0 * G4 + n0), v0);
            __stcg((float2*)(dst + (size_t)(m0 + 8) * G4 + n0), v1);
        }
    }
}

// ---------------------------------------------------------------------------
// Cell: reduce 4 K-slot partials + bias, LSTM gates + done-mask; emit bf16
// splits of unmasked (layer0) and masked h for next-step GEMMs.
// ---------------------------------------------------------------------------
__device__ void cell_phase(const float* __restrict__ gp,
                           const float* __restrict__ bias,
                           const float* __restrict__ done_t,
                           int layer, float* __restrict__ out_un)
{
    const int tg = blockIdx.x * NTHR + threadIdx.x;   // 0..32767
    const int idx = tg * 4;
    const int b = idx >> 9;
    const int j = idx & 511;
    const float m = 1.0f - __ldg(done_t + b);

    float4 G[4];
#pragma unroll
    for (int g = 0; g < 4; g++) {
        const size_t o = (size_t)b * G4 + g * 512 + j;
        float4 s0 = __ldcg((const float4*)(gp + 0 * (size_t)GPSTRIDE + o));
        float4 s1 = __ldcg((const float4*)(gp + 1 * (size_t)GPSTRIDE + o));
        float4 s2 = __ldcg((const float4*)(gp + 2 * (size_t)GPSTRIDE + o));
        float4 s3 = __ldcg((const float4*)(gp + 3 * (size_t)GPSTRIDE + o));
        float4 bb = __ldg((const float4*)&bias[g * 512 + j]);
        G[g].x = s0.x + s1.x + s2.x + s3.x + bb.x;
        G[g].y = s0.y + s1.y + s2.y + s3.y + bb.y;
        G[g].z = s0.z + s1.z + s2.z + s3.z + bb.z;
        G[g].w = s0.w + s1.w + s2.w + s3.w + bb.w;
    }

    float4 cp = __ldcg((const float4*)&d_c[layer][idx]);
    float4 hn, hm, cm;
    {
        float cn;
        cn   = sigf(G[1].x) * cp.x + sigf(G[0].x) * tanhfast(G[2].x);
        hn.x = sigf(G[3].x) * tanhfast(cn);  cm.x = cn * m;
        cn   = sigf(G[1].y) * cp.y + sigf(G[0].y) * tanhfast(G[2].y);
        hn.y = sigf(G[3].y) * tanhfast(cn);  cm.y = cn * m;
        cn   = sigf(G[1].z) * cp.z + sigf(G[0].z) * tanhfast(G[2].z);
        hn.z = sigf(G[3].z) * tanhfast(cn);  cm.z = cn * m;
        cn   = sigf(G[1].w) * cp.w + sigf(G[0].w) * tanhfast(G[2].w);
        hn.w = sigf(G[3].w) * tanhfast(cn);  cm.w = cn * m;
    }
    hm.x = hn.x * m; hm.y = hn.y * m; hm.z = hn.z * m; hm.w = hn.w * m;

    if (layer == 0) {
        uint2 uh, ul;
        split4(hn, uh, ul);                       // unmasked -> layer1 input
        __stcg((uint2*)&d_unh[idx], uh);
        __stcg((uint2*)&d_unl[idx], ul);
    } else {
        __stcg((float4*)(out_un + idx), hn);      // unmasked -> output slab
    }
    uint2 mh, ml;
    split4(hm, mh, ml);                           // masked carry splits
    __stcg((uint2*)&d_hh[layer][idx], mh);
    __stcg((uint2*)&d_hl[layer][idx], ml);
    __stcg((float4*)&d_h[layer][idx], hm);        // fp32 (final output)
    __stcg((float4*)&d_c[layer][idx], cm);
}

// ---------------------------------------------------------------------------
__global__ __launch_bounds__(NTHR, 1) void lstm_mma(
    const float* __restrict__ x,    const float* __restrict__ h0,
    const float* __restrict__ c0,   const float* __restrict__ done,
    const float* __restrict__ Wih0, const float* __restrict__ Whh0,
    const float* __restrict__ bih0, const float* __restrict__ bhh0,
    const float* __restrict__ Wih1, const float* __restrict__ Whh1,
    const float* __restrict__ bih1, const float* __restrict__ bhh1,
    float* __restrict__ out)
{
    extern __shared__ char smraw[];
    char* sm = (char*)(((uintptr_t)smraw + 1023) & ~(uintptr_t)1023);
    uint32_t sb;
    asm("{ .reg .u64 t; cvta.to.shared.u64 t, %1; cvt.u32.u64 %0, t; }"
        : "=r"(sb) : "l"(sm));

    const int tid = threadIdx.x;
    const int tg = blockIdx.x * NTHR + tid;

    // ================= prologue: conversions (once per launch) =============
    for (int i4 = tg; i4 < SBI / 4; i4 += NCTA * NTHR) {
        float4 v = __ldg((const float4*)(x + (size_t)i4 * 4));
        uint2 hi, lo;
        split4(v, hi, lo);
        __stcg((uint2*)&d_xh[(size_t)i4 * 4], hi);
        __stcg((uint2*)&d_xl[(size_t)i4 * 4], lo);
    }
    for (int i = tg; i < G4 * 768; i += NCTA * NTHR) {
        const int n = i / 768, k = i - n * 768;
        const float v = (k < 256) ? __ldg(Wih0 + n * 256 + k)
                                  : __ldg(Whh0 + n * 512 + (k - 256));
        __nv_bfloat16 h, l;
        split1(v, h, l);
        d_W0h[i] = h; d_W0l[i] = l;
    }
    for (int i = tg; i < G4 * 1024; i += NCTA * NTHR) {
        const int n = i >> 10, k = i & 1023;
        const float v = (k < 512) ? __ldg(Wih1 + n * 512 + k)
                                  : __ldg(Whh1 + n * 512 + (k - 512));
        __nv_bfloat16 h, l;
        split1(v, h, l);
        d_W1h[i] = h; d_W1l[i] = l;
    }
    {
        const int idx = tg * 4;
#pragma unroll
        for (int l = 0; l < 2; l++) {
            float4 hv = __ldg((const float4*)(h0 + (size_t)l * BH + idx));
            float4 cv = __ldg((const float4*)(c0 + (size_t)l * BH + idx));
            __stcg((float4*)&d_h[l][idx], hv);
            __stcg((float4*)&d_c[l][idx], cv);
            uint2 hi, lo;
            split4(hv, hi, lo);
            __stcg((uint2*)&d_hh[l][idx], hi);
            __stcg((uint2*)&d_hl[l][idx], lo);
        }
        if (tg < 1024) {
            const int l = tg >> 9;
            const int c4 = (tg & 511) * 4;
            const float* bi = l ? bih1 : bih0;
            const float* bh = l ? bhh1 : bhh0;
            float4 a = __ldg((const float4*)(bi + c4));
            float4 b = __ldg((const float4*)(bh + c4));
            float4 r;
            r.x = a.x + b.x; r.y = a.y + b.y; r.z = a.z + b.z; r.w = a.w + b.w;
            __stcg((float4*)&d_bias[l][c4], r);
        }
    }

    gridbar();

    // ================= main recurrence =====================================
    for (int t = 0; t < Ssz; t++) {
        gemm_mma(sb, 3, 0, t, &d_gpA[0][0]);
        gridbar();   // A: gate partials L0 complete
        cell_phase(&d_gpA[0][0], d_bias[0], done + (size_t)t * Bsz, 0, nullptr);
        gridbar();   // B: h0un / h0 splits complete
        gemm_mma(sb, 4, 1, t, &d_gpB[0][0]);
        gridbar();   // C: gate partials L1 complete
        cell_phase(&d_gpB[0][0], d_bias[1], done + (size_t)t * Bsz, 1,
                   out + (size_t)t * BH);
        // no barrier: next gemm0 (writes gpA, reads h[0]/x) is disjoint from
        // concurrent cell1 (reads gpB, writes h[1]/c[1]/out)
    }

    // ================= tail: final h, c ====================================
    {
        const int idx = tg * 4;
#pragma unroll
        for (int l = 0; l < 2; l++) {
            float4 hv = __ldcg((const float4*)&d_h[l][idx]);
            float4 cv = __ldcg((const float4*)&d_c[l][idx]);
            *(float4*)(out + (size_t)Ssz * BH + (size_t)l * BH + idx) = hv;
            *(float4*)(out + (size_t)Ssz * BH + (size_t)2 * BH
                           + (size_t)l * BH + idx) = cv;
        }
    }
}

// ---------------------------------------------------------------------------
extern "C" void kernel_launch(void* const* d_in, const int* in_sizes, int n_in,
                              void* d_out, int out_size)
{
    const float* x    = (const float*)d_in[0];
    const float* h0   = (const float*)d_in[1];
    const float* c0   = (const float*)d_in[2];
    const float* done = (const float*)d_in[3];
    const float* Wih0 = (const float*)d_in[4];
    const float* Whh0 = (const float*)d_in[5];
    const float* bih0 = (const float*)d_in[6];
    const float* bhh0 = (const float*)d_in[7];
    const float* Wih1 = (const float*)d_in[8];
    const float* Whh1 = (const float*)d_in[9];
    const float* bih1 = (const float*)d_in[10];
    const float* bhh1 = (const float*)d_in[11];
    float* out = (float*)d_out;

    cudaFuncSetAttribute(lstm_mma, cudaFuncAttributeMaxDynamicSharedMemorySize,
                         SMEM_DYN);
    lstm_mma<<<NCTA, NTHR, SMEM_DYN>>>(x, h0, c0, done,
                                       Wih0, Whh0, bih0, bhh0,
                                       Wih1, Whh1, bih1, bhh1, out);
}